// round 9
// baseline (speedup 1.0000x reference)
#include <cuda_runtime.h>

#define BB     32
#define NATOM  256
#define NN     100
#define NF     42
#define NH     50
#define NFP    44              // NF padded to multiple of 4
#define NHP    52              // NH padded to multiple of 4
#define ROWLEN (NN * NF * 3)   // 12600 floats per (b,n)
#define ROW4   (ROWLEN / 4)    // 3150 float4
#define NGRP   (NN * NF / 4)   // 1050 groups of 12 floats = 3 float4 = 4 entries
#define GMAIN  1024            // 256 threads x 4 groups
#define GLEFT  (NGRP - GMAIN)  // 26 leftover groups

// dE (grad of sum Ei wrt image), [B, NATOM, NF]. Device global => no allocation.
__device__ float g_dE[BB * NATOM * NF];
// 1 if neighbor buffer is int32, 0 if int64. Written by mlp_kernel block 0.
__device__ int   g_nbr_is32;

__device__ __forceinline__ float safe_tanh(float x) {
    // tanh(x) = 1 - 2/(exp(2x)+1); exact saturation at +/-inf, ~1e-6 accurate.
    float e = __expf(2.0f * x);
    return 1.0f - 2.0f / (e + 1.0f);
}

// ---------------------------------------------------------------------------
// Kernel 1: warp-per-atom MLP forward + input-gradient backward.
// Weights held in smem in BOTH padded layouts so every dot product is a
// contiguous float4 LDS.128 run (conflict-free: row strides 176B/208B are
// coprime-ish with the 128B bank window).
// Block 0 additionally detects the neighbor dtype (int32 vs int64): values
// are in [0,256], so for little-endian int64 every odd 32-bit word is 0.
// ---------------------------------------------------------------------------
// smem float offsets (all 16B-aligned)
#define W0P 0                          // [NF][NHP]  W0 row-major padded  (2184)
#define W0T 2184                       // [NH][NFP]  W0 transposed padded (2200)
#define W1P 4384                       // [NH][NHP]  W1 row-major padded  (2600)
#define W1T 6984                       // [NH][NHP]  W1 transposed padded (2600)
#define W2O 9584                       // [NHP]                             (52)
#define SCR 9636                       // 8 warps x (NFP + NHP + NHP = 148) (1184)
#define B0O 10820                      // [NH]
#define B1O 10870                      // [NH]
#define SMEMF 10920

__global__ void __launch_bounds__(256) mlp_kernel(
    const float* __restrict__ image,
    const unsigned int* __restrict__ nbr_words,
    const float* __restrict__ W0a, const float* __restrict__ b0a,
    const float* __restrict__ W1a, const float* __restrict__ b1a,
    const float* __restrict__ W2a, const float* __restrict__ b2a,
    const float* __restrict__ W0b, const float* __restrict__ b0b,
    const float* __restrict__ W1b, const float* __restrict__ b1b,
    const float* __restrict__ W2b, const float* __restrict__ b2b,
    float* __restrict__ Ei)
{
    __shared__ __align__(16) float sm[SMEMF];
    __shared__ int s_any;

    const int tid  = threadIdx.x;
    const int warp = tid >> 5;
    const int lane = tid & 31;
    const int abase = blockIdx.x * 8;
    const int type  = ((abase % NATOM) >= 128) ? 1 : 0;

    const float* W0 = type ? W0b : W0a;
    const float* b0 = type ? b0b : b0a;
    const float* W1 = type ? W1b : W1a;
    const float* b1 = type ? b1b : b1a;
    const float* W2 = type ? W2b : W2a;
    const float  b2v = type ? b2b[0] : b2a[0];

    // neighbor-dtype detection (block 0 only), overlapped with zero phase
    int any = 0;
    if (blockIdx.x == 0) {
        if (tid == 0) s_any = 0;
        for (int i = tid; i < 4096; i += 256)
            if (nbr_words[2 * i + 1] != 0u) any = 1;
    }

    // zero the padded weight + scratch region (pads must read as 0)
    for (int i = tid; i < B0O; i += 256) sm[i] = 0.0f;
    __syncthreads();

    if (blockIdx.x == 0 && any) atomicOr(&s_any, 1);

    // load weights into both layouts
    for (int idx = tid; idx < NF * NH; idx += 256) {
        const int f = idx / NH, j = idx - f * NH;
        const float v = W0[idx];
        sm[W0P + f * NHP + j] = v;
        sm[W0T + j * NFP + f] = v;
    }
    for (int idx = tid; idx < NH * NH; idx += 256) {
        const int i = idx / NH, j = idx - i * NH;
        const float v = W1[idx];
        sm[W1P + i * NHP + j] = v;
        sm[W1T + j * NHP + i] = v;
    }
    if (tid < NH) {
        sm[W2O + tid] = W2[tid];
        sm[B0O + tid] = b0[tid];
        sm[B1O + tid] = b1[tid];
    }
    __syncthreads();

    if (blockIdx.x == 0 && tid == 0) g_nbr_is32 = s_any;

    const int a = abase + warp;                 // global atom 0..8191
    float* sx  = sm + SCR + warp * (NFP + 2 * NHP);
    float* sh0 = sx + NFP;
    float* sh1 = sh0 + NHP;
    const float4* x4  = (const float4*)sx;
    const float4* h04 = (const float4*)sh0;
    const float4* h14 = (const float4*)sh1;

    for (int f = lane; f < NF; f += 32) sx[f] = image[(size_t)a * NF + f];
    __syncwarp();

    // h0[j] = tanh(b0[j] + sum_f x[f] W0[f][j])   (W0T row j, contiguous f)
    for (int j = lane; j < NH; j += 32) {
        const float4* wr = (const float4*)(sm + W0T + j * NFP);
        float s = sm[B0O + j];
        #pragma unroll
        for (int t = 0; t < NFP / 4; t++) {
            const float4 w = wr[t], x = x4[t];
            s += w.x * x.x + w.y * x.y + w.z * x.z + w.w * x.w;
        }
        sh0[j] = safe_tanh(s);
    }
    __syncwarp();

    // h1[j] = tanh(b1[j] + sum_i h0[i] W1[i][j])  (W1T row j, contiguous i)
    for (int j = lane; j < NH; j += 32) {
        const float4* wr = (const float4*)(sm + W1T + j * NHP);
        float s = sm[B1O + j];
        #pragma unroll
        for (int t = 0; t < NHP / 4; t++) {
            const float4 w = wr[t], h = h04[t];
            s += w.x * h.x + w.y * h.y + w.z * h.z + w.w * h.w;
        }
        sh1[j] = safe_tanh(s);
    }
    __syncwarp();

    // y = h1 . W2 + b2
    float t = 0.0f;
    for (int j = lane; j < NH; j += 32) t += sh1[j] * sm[W2O + j];
    #pragma unroll
    for (int o = 16; o > 0; o >>= 1) t += __shfl_down_sync(0xffffffffu, t, o);
    if (lane == 0) Ei[a] = t + b2v;
    __syncwarp();

    // g1[j] = W2[j] * (1 - h1^2)   (overwrite sh1; pads stay 0)
    for (int j = lane; j < NH; j += 32) {
        const float h = sh1[j];
        sh1[j] = sm[W2O + j] * (1.0f - h * h);
    }
    __syncwarp();

    // g0[i] = (sum_j W1[i][j] g1[j]) * (1 - h0^2)  (W1P row i, contiguous j)
    for (int i = lane; i < NH; i += 32) {
        const float4* wr = (const float4*)(sm + W1P + i * NHP);
        float s = 0.0f;
        #pragma unroll
        for (int tt = 0; tt < NHP / 4; tt++) {
            const float4 w = wr[tt], g = h14[tt];
            s += w.x * g.x + w.y * g.y + w.z * g.z + w.w * g.w;
        }
        const float h = sh0[i];
        sh0[i] = s * (1.0f - h * h);
    }
    __syncwarp();

    // dx[f] = sum_i W0[f][i] g0[i]                 (W0P row f, contiguous i)
    for (int f = lane; f < NF; f += 32) {
        const float4* wr = (const float4*)(sm + W0P + f * NHP);
        float s = 0.0f;
        #pragma unroll
        for (int tt = 0; tt < NHP / 4; tt++) {
            const float4 w = wr[tt], g = h04[tt];
            s += w.x * g.x + w.y * g.y + w.z * g.z + w.w * g.w;
        }
        g_dE[(size_t)a * NF + f] = s;
    }
}

// ---------------------------------------------------------------------------
// Kernel 2: deterministic Etot = sum_n Ei[b, n]
// ---------------------------------------------------------------------------
__global__ void __launch_bounds__(256) etot_kernel(
    const float* __restrict__ Ei, float* __restrict__ Etot)
{
    __shared__ float s[256];
    const int b = blockIdx.x;
    s[threadIdx.x] = Ei[b * NATOM + threadIdx.x];
    __syncthreads();
    #pragma unroll
    for (int o = 128; o > 0; o >>= 1) {
        if (threadIdx.x < o) s[threadIdx.x] += s[threadIdx.x + o];
        __syncthreads();
    }
    if (threadIdx.x == 0) Etot[b] = s[0];
}

// ---------------------------------------------------------------------------
// Kernel 3: Force. Group-of-12 FFMA structure as R8, but ALL dfeat LDG.128s
// are issued into registers BEFORE the dE gather, so the DRAM stream stays
// busy through the block prologue (gather + barriers hide under LDG latency).
// 1050 groups = 256 threads x 4 (constant trip, fully unrolled) + 26 leftover.
// ---------------------------------------------------------------------------
__global__ void __launch_bounds__(256, 2) force_kernel(
    const float* __restrict__ dfeat,
    const void* __restrict__ neighbor,
    float* __restrict__ force)
{
    __shared__ __align__(16) float sdE[NN * NF];   // 16.8 KB
    __shared__ int   snbr[NN];
    __shared__ float sred[3][8];

    const int tid = threadIdx.x;
    const int bn  = blockIdx.x;          // b*NATOM + n
    const int b   = bn >> 8;

    // 1. neighbor indices (dtype flag from mlp block 0)
    if (tid < NN) {
        int j;
        if (g_nbr_is32) j = ((const int*)neighbor)[(size_t)bn * NN + tid];
        else            j = (int)((const long long*)neighbor)[(size_t)bn * NN + tid];
        snbr[tid] = j;
    }

    // 2. front-batch the entire dfeat row into registers (15 LDG.128/thread max)
    const float4* __restrict__ df4 =
        (const float4*)(dfeat + (size_t)bn * ROWLEN);
    float4 v[12];
    #pragma unroll
    for (int u = 0; u < 4; u++) {
        const int g = tid + 256 * u;
        v[3 * u + 0] = df4[3 * g + 0];
        v[3 * u + 1] = df4[3 * g + 1];
        v[3 * u + 2] = df4[3 * g + 2];
    }
    float4 l0, l1, l2;
    if (tid < GLEFT) {
        const int g = GMAIN + tid;
        l0 = df4[3 * g + 0];
        l1 = df4[3 * g + 1];
        l2 = df4[3 * g + 2];
    }
    __syncthreads();

    // 3. gather dE rows for the 100 neighbors (overlapped with in-flight LDGs)
    {
        const float* dEb = g_dE + (size_t)b * NATOM * NF;
        float2* sdE2 = (float2*)sdE;
        for (int i2 = tid; i2 < NN * NF / 2; i2 += 256) {
            const int k = (2 * i2) / NF;
            const int f = 2 * i2 - k * NF;
            const int j = snbr[k];
            float2 w;
            if (j == 0) { w.x = 0.0f; w.y = 0.0f; }
            else        { w = *(const float2*)(dEb + (j - 1) * NF + f); }
            sdE2[i2] = w;
        }
    }
    __syncthreads();

    // 4. FFMA: per group, 1 LDS.128 of weights + 12 plain FFMAs
    const float4* __restrict__ sdE4 = (const float4*)sdE;
    float a0 = 0.0f, a1 = 0.0f, a2 = 0.0f;
    #pragma unroll
    for (int u = 0; u < 4; u++) {
        const int g = tid + 256 * u;
        const float4 w  = sdE4[g];
        const float4 v0 = v[3 * u + 0], v1 = v[3 * u + 1], v2 = v[3 * u + 2];
        a0 += w.x * v0.x;  a1 += w.x * v0.y;  a2 += w.x * v0.z;
        a0 += w.y * v0.w;  a1 += w.y * v1.x;  a2 += w.y * v1.y;
        a0 += w.z * v1.z;  a1 += w.z * v1.w;  a2 += w.z * v2.x;
        a0 += w.w * v2.y;  a1 += w.w * v2.z;  a2 += w.w * v2.w;
    }
    if (tid < GLEFT) {
        const int g = GMAIN + tid;
        const float4 w = sdE4[g];
        a0 += w.x * l0.x;  a1 += w.x * l0.y;  a2 += w.x * l0.z;
        a0 += w.y * l0.w;  a1 += w.y * l1.x;  a2 += w.y * l1.y;
        a0 += w.z * l1.z;  a1 += w.z * l1.w;  a2 += w.z * l2.x;
        a0 += w.w * l2.y;  a1 += w.w * l2.z;  a2 += w.w * l2.w;
    }

    #pragma unroll
    for (int o = 16; o > 0; o >>= 1) {
        a0 += __shfl_down_sync(0xffffffffu, a0, o);
        a1 += __shfl_down_sync(0xffffffffu, a1, o);
        a2 += __shfl_down_sync(0xffffffffu, a2, o);
    }
    const int warp = tid >> 5;
    if ((tid & 31) == 0) { sred[0][warp] = a0; sred[1][warp] = a1; sred[2][warp] = a2; }
    __syncthreads();

    if (tid < 3) {
        float s = 0.0f;
        #pragma unroll
        for (int w = 0; w < 8; w++) s += sred[tid][w];
        force[(size_t)bn * 3 + tid] = s;
    }
}

// ---------------------------------------------------------------------------
extern "C" void kernel_launch(void* const* d_in, const int* in_sizes, int n_in,
                              void* d_out, int out_size)
{
    const float* image    = (const float*)d_in[0];
    const float* dfeat    = (const float*)d_in[1];
    const void*  neighbor = d_in[2];
    const float* W0_0 = (const float*)d_in[3];
    const float* b0_0 = (const float*)d_in[4];
    const float* W1_0 = (const float*)d_in[5];
    const float* b1_0 = (const float*)d_in[6];
    const float* W2_0 = (const float*)d_in[7];
    const float* b2_0 = (const float*)d_in[8];
    const float* W0_1 = (const float*)d_in[9];
    const float* b0_1 = (const float*)d_in[10];
    const float* W1_1 = (const float*)d_in[11];
    const float* b1_1 = (const float*)d_in[12];
    const float* W2_1 = (const float*)d_in[13];
    const float* b2_1 = (const float*)d_in[14];

    float* out   = (float*)d_out;
    float* Etot  = out;                       // [32]
    float* Ei    = out + BB;                  // [32*256]
    float* Force = out + BB + BB * NATOM;     // [32*256*3]

    mlp_kernel<<<BB * NATOM / 8, 256>>>(
        image, (const unsigned int*)neighbor,
        W0_0, b0_0, W1_0, b1_0, W2_0, b2_0,
        W0_1, b0_1, W1_1, b1_1, W2_1, b2_1,
        Ei);
    etot_kernel<<<BB, 256>>>(Ei, Etot);
    force_kernel<<<BB * NATOM, 256>>>(dfeat, neighbor, Force);
}

// round 11
// speedup vs baseline: 1.2743x; 1.2743x over previous
#include <cuda_runtime.h>

#define BB     32
#define NATOM  256
#define NN     100
#define NF     42
#define NH1    50
#define NH2    50
#define ROWLEN (NN * NF * 3)          // 12600 floats per (b,n)
#define NGRP   (NN * NF / 4)          // 1050 groups of 12 floats (= 3 float4 = 4 entries)

// dE (grad of sum Ei wrt image), [B, NATOM, NF]. Device global => no allocation.
__device__ float g_dE[BB * NATOM * NF];
// 1 if neighbor buffer is int32, 0 if int64. Written by mlp_kernel block 0.
__device__ int   g_nbr_is32;

__device__ __forceinline__ float safe_tanh(float x) {
    // tanh(x) = 1 - 2/(exp(2x)+1); exact saturation at +/-inf, ~1e-6 accurate.
    float e = __expf(2.0f * x);
    return 1.0f - 2.0f / (e + 1.0f);
}

// ---------------------------------------------------------------------------
// Kernel 1: warp-per-atom MLP forward + input-gradient backward.
// Block = 256 threads = 8 warps = 8 atoms (all same type: 8 | 128).
// Block 0 also detects the neighbor dtype: values are in [0,256], so for
// little-endian int64 every odd 32-bit word is 0; for int32 essentially never.
// ---------------------------------------------------------------------------
__global__ void __launch_bounds__(256) mlp_kernel(
    const float* __restrict__ image,
    const unsigned int* __restrict__ nbr_words,
    const float* __restrict__ W0a, const float* __restrict__ b0a,
    const float* __restrict__ W1a, const float* __restrict__ b1a,
    const float* __restrict__ W2a, const float* __restrict__ b2a,
    const float* __restrict__ W0b, const float* __restrict__ b0b,
    const float* __restrict__ W1b, const float* __restrict__ b1b,
    const float* __restrict__ W2b, const float* __restrict__ b2b,
    float* __restrict__ Ei)
{
    __shared__ float sW0[NF * NH1];
    __shared__ float sW1[NH1 * NH2];
    __shared__ float sW2[NH2];
    __shared__ float sb0[NH1];
    __shared__ float sb1[NH2];
    __shared__ float scratch[8][NF + NH1 + NH2];
    __shared__ int s_any;

    const int tid  = threadIdx.x;
    const int warp = tid >> 5;
    const int lane = tid & 31;
    const int abase = blockIdx.x * 8;           // global atom base
    const int type  = ((abase % NATOM) >= 128) ? 1 : 0;

    const float* W0 = type ? W0b : W0a;
    const float* b0 = type ? b0b : b0a;
    const float* W1 = type ? W1b : W1a;
    const float* b1 = type ? b1b : b1a;
    const float* W2 = type ? W2b : W2a;
    const float  b2v = type ? b2b[0] : b2a[0];

    // neighbor-dtype detection (block 0 only), overlapped with weight loads
    int any = 0;
    if (blockIdx.x == 0) {
        if (tid == 0) s_any = 0;
        for (int i = tid; i < 4096; i += 256)
            if (nbr_words[2 * i + 1] != 0u) any = 1;
    }

    for (int i = tid; i < NF * NH1; i += 256)  sW0[i] = W0[i];
    for (int i = tid; i < NH1 * NH2; i += 256) sW1[i] = W1[i];
    if (tid < NH2) sW2[tid] = W2[tid];
    if (tid < NH1) sb0[tid] = b0[tid];
    if (tid < NH2) sb1[tid] = b1[tid];
    __syncthreads();

    if (blockIdx.x == 0) {
        if (any) atomicOr(&s_any, 1);
        __syncthreads();
        if (tid == 0) g_nbr_is32 = s_any;
    }

    const int a = abase + warp;                 // global atom 0..8191
    float* sx  = scratch[warp];
    float* sh0 = sx + NF;
    float* sh1 = sh0 + NH1;

    // load x
    for (int f = lane; f < NF; f += 32) sx[f] = image[(size_t)a * NF + f];
    __syncwarp();

    // h0 = tanh(x W0 + b0)
    for (int j = lane; j < NH1; j += 32) {
        float s = sb0[j];
        #pragma unroll
        for (int f = 0; f < NF; f++) s += sx[f] * sW0[f * NH1 + j];
        sh0[j] = safe_tanh(s);
    }
    __syncwarp();

    // h1 = tanh(h0 W1 + b1)
    for (int j = lane; j < NH2; j += 32) {
        float s = sb1[j];
        #pragma unroll
        for (int i = 0; i < NH1; i++) s += sh0[i] * sW1[i * NH2 + j];
        sh1[j] = safe_tanh(s);
    }
    __syncwarp();

    // y = h1 . W2 + b2   (warp reduction)
    float t = 0.0f;
    for (int j = lane; j < NH2; j += 32) t += sh1[j] * sW2[j];
    #pragma unroll
    for (int o = 16; o > 0; o >>= 1) t += __shfl_down_sync(0xffffffffu, t, o);
    if (lane == 0) Ei[a] = t + b2v;
    __syncwarp();

    // backward: g1 = W2 * (1 - h1^2), overwrite sh1
    for (int j = lane; j < NH2; j += 32) {
        float h = sh1[j];
        sh1[j] = sW2[j] * (1.0f - h * h);
    }
    __syncwarp();

    // g0 = (W1 g1) * (1 - h0^2), overwrite sh0
    for (int i = lane; i < NH1; i += 32) {
        float s = 0.0f;
        #pragma unroll
        for (int j = 0; j < NH2; j++) s += sW1[i * NH2 + j] * sh1[j];
        float h = sh0[i];
        sh0[i] = s * (1.0f - h * h);
    }
    __syncwarp();

    // dx = W0 g0
    for (int f = lane; f < NF; f += 32) {
        float s = 0.0f;
        #pragma unroll
        for (int i = 0; i < NH1; i++) s += sW0[f * NH1 + i] * sh0[i];
        g_dE[(size_t)a * NF + f] = s;
    }
}

// ---------------------------------------------------------------------------
// Kernel 2: deterministic Etot = sum_n Ei[b, n]
// ---------------------------------------------------------------------------
__global__ void __launch_bounds__(256) etot_kernel(
    const float* __restrict__ Ei, float* __restrict__ Etot)
{
    __shared__ float s[256];
    const int b = blockIdx.x;
    s[threadIdx.x] = Ei[b * NATOM + threadIdx.x];
    __syncthreads();
    #pragma unroll
    for (int o = 128; o > 0; o >>= 1) {
        if (threadIdx.x < o) s[threadIdx.x] += s[threadIdx.x + o];
        __syncthreads();
    }
    if (threadIdx.x == 0) Etot[b] = s[0];
}

// ---------------------------------------------------------------------------
// Kernel 3: Force[b,n,d] = sum_{k,f} dE_pad[b, nbr[b,n,k], f] * dfeat[b,n,k,f,d]
// One block per (b,n). Group-of-12 structure (lcm(3,4)=12): per group,
// 1 LDS.128 of 4 weights + 3 LDG.128 + 12 plain FFMAs, zero div/mod.
// (Exact R8 configuration: regs ~30, 8 CTAs/SM — do not add reg pressure.)
// ---------------------------------------------------------------------------
__global__ void __launch_bounds__(256) force_kernel(
    const float* __restrict__ dfeat,
    const void* __restrict__ neighbor,
    float* __restrict__ force)
{
    __shared__ __align__(16) float sdE[NN * NF];   // 4200 floats = 16.8 KB
    __shared__ int   snbr[NN];
    __shared__ float sred[3][8];

    const int tid = threadIdx.x;
    const int bn  = blockIdx.x;          // b*NATOM + n
    const int b   = bn >> 8;

    if (tid < NN) {
        int j;
        if (g_nbr_is32) j = ((const int*)neighbor)[(size_t)bn * NN + tid];
        else            j = (int)((const long long*)neighbor)[(size_t)bn * NN + tid];
        snbr[tid] = j;
    }
    __syncthreads();

    // Gather dE rows for the 100 neighbors (0 => padded zero row, j => atom j-1).
    // float2-vectorized: rows are 42 floats, pairs never straddle a row.
    {
        const float* dEb = g_dE + (size_t)b * NATOM * NF;
        float2* sdE2 = (float2*)sdE;
        for (int i2 = tid; i2 < NN * NF / 2; i2 += 256) {
            const int k  = (2 * i2) / NF;
            const int f  = 2 * i2 - k * NF;
            const int j  = snbr[k];
            float2 v;
            if (j == 0) { v.x = 0.0f; v.y = 0.0f; }
            else        { v = *(const float2*)(dEb + (j - 1) * NF + f); }
            sdE2[i2] = v;
        }
    }
    __syncthreads();

    // Stream dfeat row: thread handles group g (= floats [12g, 12g+12)).
    const float4* __restrict__ df4 =
        (const float4*)(dfeat + (size_t)bn * ROWLEN);
    const float4* __restrict__ sdE4 = (const float4*)sdE;

    float a0 = 0.0f, a1 = 0.0f, a2 = 0.0f;
    for (int g = tid; g < NGRP; g += 256) {
        const float4 w  = sdE4[g];           // weights for entries 4g..4g+3
        const float4 v0 = df4[3 * g + 0];
        const float4 v1 = df4[3 * g + 1];
        const float4 v2 = df4[3 * g + 2];
        // entry 4g
        a0 += w.x * v0.x;  a1 += w.x * v0.y;  a2 += w.x * v0.z;
        // entry 4g+1
        a0 += w.y * v0.w;  a1 += w.y * v1.x;  a2 += w.y * v1.y;
        // entry 4g+2
        a0 += w.z * v1.z;  a1 += w.z * v1.w;  a2 += w.z * v2.x;
        // entry 4g+3
        a0 += w.w * v2.y;  a1 += w.w * v2.z;  a2 += w.w * v2.w;
    }

    #pragma unroll
    for (int o = 16; o > 0; o >>= 1) {
        a0 += __shfl_down_sync(0xffffffffu, a0, o);
        a1 += __shfl_down_sync(0xffffffffu, a1, o);
        a2 += __shfl_down_sync(0xffffffffu, a2, o);
    }
    const int warp = tid >> 5;
    if ((tid & 31) == 0) { sred[0][warp] = a0; sred[1][warp] = a1; sred[2][warp] = a2; }
    __syncthreads();

    if (tid < 3) {
        float s = 0.0f;
        #pragma unroll
        for (int w = 0; w < 8; w++) s += sred[tid][w];
        force[(size_t)bn * 3 + tid] = s;
    }
}

// ---------------------------------------------------------------------------
extern "C" void kernel_launch(void* const* d_in, const int* in_sizes, int n_in,
                              void* d_out, int out_size)
{
    const float* image    = (const float*)d_in[0];
    const float* dfeat    = (const float*)d_in[1];
    const void*  neighbor = d_in[2];
    const float* W0_0 = (const float*)d_in[3];
    const float* b0_0 = (const float*)d_in[4];
    const float* W1_0 = (const float*)d_in[5];
    const float* b1_0 = (const float*)d_in[6];
    const float* W2_0 = (const float*)d_in[7];
    const float* b2_0 = (const float*)d_in[8];
    const float* W0_1 = (const float*)d_in[9];
    const float* b0_1 = (const float*)d_in[10];
    const float* W1_1 = (const float*)d_in[11];
    const float* b1_1 = (const float*)d_in[12];
    const float* W2_1 = (const float*)d_in[13];
    const float* b2_1 = (const float*)d_in[14];

    float* out   = (float*)d_out;
    float* Etot  = out;                       // [32]
    float* Ei    = out + BB;                  // [32*256]
    float* Force = out + BB + BB * NATOM;     // [32*256*3]

    mlp_kernel<<<BB * NATOM / 8, 256>>>(
        image, (const unsigned int*)neighbor,
        W0_0, b0_0, W1_0, b1_0, W2_0, b2_0,
        W0_1, b0_1, W1_1, b1_1, W2_1, b2_1,
        Ei);
    etot_kernel<<<BB, 256>>>(Ei, Etot);
    force_kernel<<<BB * NATOM, 256>>>(dfeat, neighbor, Force);
}